// round 13
// baseline (speedup 1.0000x reference)
#include <cuda_runtime.h>
#include <cuda_fp16.h>
#include <cstdint>

#define NB 64
#define NT 2048
#define NM 1024
#define NA 512
#define NQ 1024

#define BM 64             // t-rows per CTA
#define KC 64             // k per stage (fp16: 4 MMA k-steps)
#define NCHUNK (NM / KC)  // 16
#define RS 36             // smem row stride in uints: conflict-free (shift 4/row), 16B-aligned
#define NBST 2            // B stages

#define A_ST (BM * RS)                   // 2304 uints per A stage
#define B_ST (NA * RS)                   // 18432 uints per B stage
#define OFF_A 0
#define OFF_B (2 * A_ST)                 // 4608
#define OFF_WQ (OFF_B + NBST * B_ST)     // floats from here
#define OFF_WV (OFF_WQ + NA)
#define OFF_SP (OFF_WV + NA)
#define OFF_ES (OFF_SP + 16 * 64)        // 64 exp(score) values
#define OFF_FLAG (OFF_ES + 64)           // 1 int (last-CTA counter value)
#define SMEM_WORDS (OFF_FLAG + 4)
#define SMEM_SZ (SMEM_WORDS * 4)         // ~171 KB

#define NSLICE (NT / BM)                 // 32 t-slices per batch

__device__ float g_wq[NB * NA];
__device__ uint32_t g_wm_h[NA * NM / 2];        // Wm as half2 pairs, [a][k/2]
__device__ float g_ctxp[NSLICE * NB * NM];      // context partials [slice][b][m]
__device__ int g_cnt[NB];                       // per-b completion counters (reset in-kernel)

__device__ __forceinline__ uint32_t smem_u32(const void* p) {
    uint32_t a;
    asm("{ .reg .u64 t; cvta.to.shared.u64 t, %1; cvt.u32.u64 %0, t; }" : "=r"(a) : "l"(p));
    return a;
}

__device__ __forceinline__ void cpasync16(uint32_t dst, const void* src) {
    asm volatile("cp.async.cg.shared.global [%0], [%1], 16;" :: "r"(dst), "l"(src) : "memory");
}

__device__ __forceinline__ uint32_t pack_h2(float x, float y) {
    __half2 h = __floats2half2_rn(x, y);
    return *(uint32_t*)&h;
}

__device__ __forceinline__ void mma_f16(float& d0, float& d1, float& d2, float& d3,
                                        unsigned a0, unsigned a1, unsigned a2, unsigned a3,
                                        unsigned b0, unsigned b1) {
    asm("mma.sync.aligned.m16n8k16.row.col.f32.f16.f16.f32 "
        "{%0,%1,%2,%3},{%4,%5,%6,%7},{%8,%9},{%0,%1,%2,%3};"
        : "+f"(d0), "+f"(d1), "+f"(d2), "+f"(d3)
        : "r"(a0), "r"(a1), "r"(a2), "r"(a3), "r"(b0), "r"(b1));
}

#define LDMX4(r0, r1, r2, r3, addr) \
    asm volatile("ldmatrix.sync.aligned.m8n8.x4.shared.b16 {%0,%1,%2,%3}, [%4];" \
                 : "=r"(r0), "=r"(r1), "=r"(r2), "=r"(r3) : "r"(addr))

// ---------------------------------------------------------------------------
// Kernel 0 (fused prep): blocks <256 convert Wm -> fp16; blocks >=256 do wq.
// wq shape: 128 blocks x 256 thr, thread = one (b, a) dot, no smem, no idle.
// ---------------------------------------------------------------------------
__global__ __launch_bounds__(256) void prep_kernel(
    const float* __restrict__ Wm, const float* __restrict__ query,
    const float* __restrict__ Wq)
{
    int bid = blockIdx.x;
    if (bid < 256) {
        int i = bid * 256 + threadIdx.x;
        const float4* s = (const float4*)Wm;
        float4 v0 = s[2 * i], v1 = s[2 * i + 1];
        g_wm_h[4 * i + 0] = pack_h2(v0.x, v0.y);
        g_wm_h[4 * i + 1] = pack_h2(v0.z, v0.w);
        g_wm_h[4 * i + 2] = pack_h2(v1.x, v1.y);
        g_wm_h[4 * i + 3] = pack_h2(v1.z, v1.w);
    } else {
        int id = bid - 256;                  // 0..127
        int b = id >> 1, a = (id & 1) * 256 + threadIdx.x;
        const float4* q4 = (const float4*)(query + b * NQ);
        const float4* w4 = (const float4*)(Wq + (size_t)a * NQ);
        float s = 0.f;
#pragma unroll 8
        for (int k = 0; k < NQ / 4; k++) {
            float4 q = q4[k], w = w4[k];
            s += q.x * w.x + q.y * w.y + q.z * w.z + q.w * w.w;
        }
        g_wq[b * NA + a] = s;
    }
}

// ---------------------------------------------------------------------------
// Kernel 2: fused fp16 mma.sync GEMM (64 x 512 x 1024) + Wv.tanh(wq+wm)
//           + exp + context partial + LAST-CTA-PER-B finalize (Z, normalize,
//           context reduce) -- no separate finalize kernel.
// KC=64: 16 chunks. Single-depth B pipeline (R10 structure, measured best).
// ---------------------------------------------------------------------------
__device__ __forceinline__ void issue_B(int c, uint32_t bbuf, int tid) {
    int k2 = c * (KC / 2);                    // uint offset within row
#pragma unroll
    for (int i = 0; i < 8; i++) {             // 512 rows x 8 x 16B = 64KB
        int e = tid + i * 512;
        int row = e >> 3, c16 = e & 7;
        cpasync16(bbuf + (row * RS + c16 * 4) * 4,
                  g_wm_h + (size_t)row * (NM / 2) + k2 + c16 * 4);
    }
    asm volatile("cp.async.commit_group;" ::: "memory");
}

__global__ __launch_bounds__(512, 1) void score_kernel(
    const float* __restrict__ mem, const float* __restrict__ Wv,
    float* __restrict__ alpha_un, float* __restrict__ ctx)
{
    extern __shared__ __align__(16) uint32_t smem[];
    uint32_t sbase = smem_u32(smem);
    float* wqs = (float*)(smem + OFF_WQ);
    float* wvs = (float*)(smem + OFF_WV);
    float* spr = (float*)(smem + OFF_SP);
    float* es  = (float*)(smem + OFF_ES);

    int tid = threadIdx.x, wid = tid >> 5, lane = tid & 31;
    int g = lane >> 2, tg = lane & 3;
    int b = blockIdx.y, t0 = blockIdx.x * BM;

    for (int i = tid; i < NA; i += 512) {
        wqs[i] = g_wq[b * NA + i];
        wvs[i] = Wv[i];
    }

    const float* Ag = mem + ((size_t)b * NT + t0) * NM;
    const int arow = tid >> 3, ac = tid & 7;   // A: 64 rows x 8 float4-pairs

    // ldmatrix lane-address components (uint offsets within a stage)
    int q8 = lane >> 3, r8 = lane & 7;
    int aoff = ((q8 & 1) * 8 + r8) * RS + (q8 >> 1) * 4;
    int boff = ((q8 & 2) * 4 + r8 + wid * 32) * RS + (q8 & 1) * 4;

    float acc[4][4][4];
#pragma unroll
    for (int mf = 0; mf < 4; mf++)
#pragma unroll
        for (int j = 0; j < 4; j++)
#pragma unroll
            for (int qq = 0; qq < 4; qq++) acc[mf][j][qq] = 0.f;

    // prologue: A(0) in regs; B(0) in flight
    float4 ar0 = *(const float4*)(Ag + (size_t)arow * NM + ac * 8);
    float4 ar1 = *(const float4*)(Ag + (size_t)arow * NM + ac * 8 + 4);
    issue_B(0, sbase + (OFF_B + 0 * B_ST) * 4, tid);

    for (int c = 0; c < NCHUNK; c++) {
        asm volatile("cp.async.wait_group 0;" ::: "memory");   // B(c) landed
        // store A(c) from regs (fp16, 8 cols -> uint4)
        {
            uint32_t* Ab = smem + OFF_A + (c & 1) * A_ST;
            uint4 u;
            u.x = pack_h2(ar0.x, ar0.y);
            u.y = pack_h2(ar0.z, ar0.w);
            u.z = pack_h2(ar1.x, ar1.y);
            u.w = pack_h2(ar1.z, ar1.w);
            *(uint4*)(Ab + arow * RS + ac * 4) = u;
        }
        __syncthreads();   // B(c)+A(c) visible; buf (c+1)&1 fully consumed
        if (c < NCHUNK - 1) {
            issue_B(c + 1, sbase + (OFF_B + ((c + 1) & 1) * B_ST) * 4, tid);
            int k0 = (c + 1) * KC;
            ar0 = *(const float4*)(Ag + (size_t)arow * NM + k0 + ac * 8);
            ar1 = *(const float4*)(Ag + (size_t)arow * NM + k0 + ac * 8 + 4);
        }

        uint32_t Abase = sbase + (OFF_A + (c & 1) * A_ST + aoff) * 4;
        uint32_t Bbase = sbase + (OFF_B + (c & 1) * B_ST + boff) * 4;
#pragma unroll
        for (int ks = 0; ks < 4; ks++) {
            int ko4 = ks * 8 * 4;   // byte offset for this k16 step
            unsigned af[4][4];
#pragma unroll
            for (int mf = 0; mf < 4; mf++)
                LDMX4(af[mf][0], af[mf][1], af[mf][2], af[mf][3],
                      Abase + ko4 + mf * 16 * RS * 4);
            unsigned bf[8];
            LDMX4(bf[0], bf[1], bf[2], bf[3], Bbase + ko4);
            LDMX4(bf[4], bf[5], bf[6], bf[7], Bbase + ko4 + 16 * RS * 4);
#pragma unroll
            for (int j = 0; j < 4; j++) {
                unsigned b0 = bf[j * 2], b1 = bf[j * 2 + 1];
#pragma unroll
                for (int mf = 0; mf < 4; mf++)
                    mma_f16(acc[mf][j][0], acc[mf][j][1], acc[mf][j][2], acc[mf][j][3],
                            af[mf][0], af[mf][1], af[mf][2], af[mf][3], b0, b1);
            }
        }
    }

    // epilogue 1: partial score rows for this warp's 32 cols
    float p0[4], p1[4];
#pragma unroll
    for (int mf = 0; mf < 4; mf++) { p0[mf] = 0.f; p1[mf] = 0.f; }
#pragma unroll
    for (int mf = 0; mf < 4; mf++)
#pragma unroll
        for (int j = 0; j < 4; j++) {
            int a0 = wid * 32 + j * 8 + 2 * tg;
            float w0 = wvs[a0], w1 = wvs[a0 + 1];
            float q0 = wqs[a0], q1 = wqs[a0 + 1];
            p0[mf] += w0 * tanhf(q0 + acc[mf][j][0]) + w1 * tanhf(q1 + acc[mf][j][1]);
            p1[mf] += w0 * tanhf(q0 + acc[mf][j][2]) + w1 * tanhf(q1 + acc[mf][j][3]);
        }
#pragma unroll
    for (int mf = 0; mf < 4; mf++) {
        p0[mf] += __shfl_xor_sync(0xffffffffu, p0[mf], 1);
        p0[mf] += __shfl_xor_sync(0xffffffffu, p0[mf], 2);
        p1[mf] += __shfl_xor_sync(0xffffffffu, p1[mf], 1);
        p1[mf] += __shfl_xor_sync(0xffffffffu, p1[mf], 2);
    }
    if (tg == 0) {
#pragma unroll
        for (int mf = 0; mf < 4; mf++) {
            spr[wid * 64 + mf * 16 + g]     = p0[mf];
            spr[wid * 64 + mf * 16 + 8 + g] = p1[mf];
        }
    }
    __syncthreads();
    if (tid < BM) {
        float s = 0.f;
#pragma unroll
        for (int w = 0; w < 16; w++) s += spr[w * 64 + tid];
        float e = expf(s);                       // no max-subtract: bounded
        alpha_un[b * NT + t0 + tid] = e;
        es[tid] = e;
    }
    __syncthreads();

    // epilogue 2: unnormalized context partial; t split across thread halves
    {
        float* pp = (float*)(smem + OFF_B);       // reuse B region (4KB)
        int half = tid >> 8;                       // 0: t<32, 1: t>=32
        int m = (tid & 255) * 4;
        const float* mp = mem + ((size_t)b * NT + t0 + half * 32) * NM + m;
        float4 cacc = {0.f, 0.f, 0.f, 0.f};
#pragma unroll 8
        for (int t = 0; t < 32; t++) {
            float e = es[half * 32 + t];
            float4 v = *(const float4*)(mp + (size_t)t * NM);
            cacc.x += e * v.x; cacc.y += e * v.y;
            cacc.z += e * v.z; cacc.w += e * v.w;
        }
        if (half) *(float4*)(pp + m) = cacc;
        __syncthreads();
        if (!half) {
            float4 o = *(const float4*)(pp + m);
            o.x += cacc.x; o.y += cacc.y; o.z += cacc.z; o.w += cacc.w;
            *(float4*)(g_ctxp + ((size_t)blockIdx.x * NB + b) * NM + m) = o;
        }
    }

    // epilogue 3: last CTA for this b finalizes (Z, normalize, context)
    __syncthreads();                             // all slice writes done CTA-wide
    if (tid == 0) {
        __threadfence();                         // publish alpha_un + g_ctxp
        ((volatile int*)smem)[OFF_FLAG] = atomicAdd(&g_cnt[b], 1);
    }
    __syncthreads();
    if (((volatile int*)smem)[OFF_FLAG] == NSLICE - 1) {
        __threadfence();                         // acquire other CTAs' data
        float* arow = alpha_un + b * NT;
        float z = 0.f;
#pragma unroll
        for (int i = 0; i < NT / 512; i++) z += arow[tid + 512 * i];
#pragma unroll
        for (int o = 16; o; o >>= 1) z += __shfl_xor_sync(0xffffffffu, z, o);
        if (lane == 0) spr[wid] = z;
        __syncthreads();
        z = 0.f;
#pragma unroll
        for (int w = 0; w < 16; w++) z += spr[w];
        float inv = 1.f / z;
#pragma unroll
        for (int i = 0; i < NT / 512; i++) arow[tid + 512 * i] *= inv;

        int m = tid * 2;
        float cx = 0.f, cy = 0.f;
#pragma unroll 4
        for (int sl = 0; sl < NSLICE; sl++) {
            float2 v = *(const float2*)(g_ctxp + ((size_t)sl * NB + b) * NM + m);
            cx += v.x; cy += v.y;
        }
        float2 o; o.x = cx * inv; o.y = cy * inv;
        *(float2*)(ctx + b * NM + m) = o;
        __syncthreads();
        if (tid == 0) g_cnt[b] = 0;              // reset for next replay
    }
}

// ---------------------------------------------------------------------------
extern "C" void kernel_launch(void* const* d_in, const int* in_sizes, int n_in,
                              void* d_out, int out_size) {
    const float* query  = (const float*)d_in[0];
    const float* memory = (const float*)d_in[1];
    const float* Wq     = (const float*)d_in[2];
    const float* Wm     = (const float*)d_in[3];
    const float* Wv     = (const float*)d_in[4];
    float* alpha = (float*)d_out;            // [64, 2048]
    float* ctx   = alpha + NB * NT;          // [64, 1024]

    prep_kernel<<<384, 256>>>(Wm, query, Wq);

    cudaFuncSetAttribute(score_kernel, cudaFuncAttributeMaxDynamicSharedMemorySize, SMEM_SZ);
    score_kernel<<<dim3(NSLICE, NB), 512, SMEM_SZ>>>(memory, Wv, alpha, ctx);
}

// round 14
// speedup vs baseline: 1.6622x; 1.6622x over previous
#include <cuda_runtime.h>
#include <cuda_fp16.h>
#include <cstdint>

#define NB 64
#define NT 2048
#define NM 1024
#define NA 512
#define NQ 1024

#define BM 64             // t-rows per CTA
#define KC 64             // k per stage (fp16: 4 MMA k-steps)
#define NCHUNK (NM / KC)  // 16
#define RS 36             // smem row stride in uints: conflict-free (shift 4/row), 16B-aligned
#define NBST 2            // B stages

#define A_ST (BM * RS)                   // 2304 uints per A stage
#define B_ST (NA * RS)                   // 18432 uints per B stage
#define OFF_A 0
#define OFF_B (2 * A_ST)                 // 4608
#define OFF_WQ (OFF_B + NBST * B_ST)     // floats from here
#define OFF_WV (OFF_WQ + NA)
#define OFF_SP (OFF_WV + NA)
#define OFF_ES (OFF_SP + 16 * 64)        // 64 exp(score) values
#define SMEM_WORDS (OFF_ES + 64)
#define SMEM_SZ (SMEM_WORDS * 4)         // ~171 KB

#define NSLICE (NT / BM)                 // 32 t-slices per batch

__device__ float g_wq[NB * NA];
__device__ uint32_t g_wm_h[NA * NM / 2];        // Wm as half2 pairs, [a][k/2]
__device__ float g_ctxp[NSLICE * NB * NM];      // context partials [slice][b][m]

__device__ __forceinline__ uint32_t smem_u32(const void* p) {
    uint32_t a;
    asm("{ .reg .u64 t; cvta.to.shared.u64 t, %1; cvt.u32.u64 %0, t; }" : "=r"(a) : "l"(p));
    return a;
}

__device__ __forceinline__ void cpasync16(uint32_t dst, const void* src) {
    asm volatile("cp.async.cg.shared.global [%0], [%1], 16;" :: "r"(dst), "l"(src) : "memory");
}

__device__ __forceinline__ uint32_t pack_h2(float x, float y) {
    __half2 h = __floats2half2_rn(x, y);
    return *(uint32_t*)&h;
}

__device__ __forceinline__ void mma_f16(float& d0, float& d1, float& d2, float& d3,
                                        unsigned a0, unsigned a1, unsigned a2, unsigned a3,
                                        unsigned b0, unsigned b1) {
    asm("mma.sync.aligned.m16n8k16.row.col.f32.f16.f16.f32 "
        "{%0,%1,%2,%3},{%4,%5,%6,%7},{%8,%9},{%0,%1,%2,%3};"
        : "+f"(d0), "+f"(d1), "+f"(d2), "+f"(d3)
        : "r"(a0), "r"(a1), "r"(a2), "r"(a3), "r"(b0), "r"(b1));
}

#define LDMX4(r0, r1, r2, r3, addr) \
    asm volatile("ldmatrix.sync.aligned.m8n8.x4.shared.b16 {%0,%1,%2,%3}, [%4];" \
                 : "=r"(r0), "=r"(r1), "=r"(r2), "=r"(r3) : "r"(addr))

// ---------------------------------------------------------------------------
// Kernel 0: convert Wm (fp32) -> g_wm_h (half2 pairs)
// ---------------------------------------------------------------------------
__global__ void cvt_wm_kernel(const float* __restrict__ Wm) {
    int i = blockIdx.x * 256 + threadIdx.x;
    const float4* s = (const float4*)Wm;
    float4 v0 = s[2 * i], v1 = s[2 * i + 1];
    g_wm_h[4 * i + 0] = pack_h2(v0.x, v0.y);
    g_wm_h[4 * i + 1] = pack_h2(v0.z, v0.w);
    g_wm_h[4 * i + 2] = pack_h2(v1.x, v1.y);
    g_wm_h[4 * i + 3] = pack_h2(v1.z, v1.w);
}

// ---------------------------------------------------------------------------
// Kernel 1: wq[b][a] = query[b] . W_query[a]  (fp32 exact; 256 CTAs x 128 thr)
// ---------------------------------------------------------------------------
__global__ __launch_bounds__(128) void wq_kernel(
    const float* __restrict__ query, const float* __restrict__ Wq)
{
    int b = blockIdx.y, a = blockIdx.x * 128 + threadIdx.x;
    const float4* q4 = (const float4*)(query + b * NQ);
    const float4* w4 = (const float4*)(Wq + a * NQ);
    float s = 0.f;
#pragma unroll 8
    for (int k = 0; k < NQ / 4; k++) {
        float4 q = q4[k], w = w4[k];
        s += q.x * w.x + q.y * w.y + q.z * w.z + q.w * w.w;
    }
    g_wq[b * NA + a] = s;
}

// ---------------------------------------------------------------------------
// Kernel 2: fused fp16 mma.sync GEMM (64 x 512 x 1024) + Wv.tanh(wq+wm)
//           + exp + unnormalized context partial.  (R10 structure: measured
//           best of 5 variants.)  KC=64, single-depth B pipeline.
// ---------------------------------------------------------------------------
__device__ __forceinline__ void issue_B(int c, uint32_t bbuf, int tid) {
    int k2 = c * (KC / 2);                    // uint offset within row
#pragma unroll
    for (int i = 0; i < 8; i++) {             // 512 rows x 8 x 16B = 64KB
        int e = tid + i * 512;
        int row = e >> 3, c16 = e & 7;
        cpasync16(bbuf + (row * RS + c16 * 4) * 4,
                  g_wm_h + (size_t)row * (NM / 2) + k2 + c16 * 4);
    }
    asm volatile("cp.async.commit_group;" ::: "memory");
}

__global__ __launch_bounds__(512, 1) void score_kernel(
    const float* __restrict__ mem, const float* __restrict__ Wv,
    float* __restrict__ alpha_un)
{
    extern __shared__ __align__(16) uint32_t smem[];
    uint32_t sbase = smem_u32(smem);
    float* wqs = (float*)(smem + OFF_WQ);
    float* wvs = (float*)(smem + OFF_WV);
    float* spr = (float*)(smem + OFF_SP);
    float* es  = (float*)(smem + OFF_ES);

    int tid = threadIdx.x, wid = tid >> 5, lane = tid & 31;
    int g = lane >> 2, tg = lane & 3;
    int b = blockIdx.y, t0 = blockIdx.x * BM;

    for (int i = tid; i < NA; i += 512) {
        wqs[i] = g_wq[b * NA + i];
        wvs[i] = Wv[i];
    }

    const float* Ag = mem + ((size_t)b * NT + t0) * NM;
    const int arow = tid >> 3, ac = tid & 7;   // A: 64 rows x 8 float4-pairs

    // ldmatrix lane-address components (uint offsets within a stage)
    int q8 = lane >> 3, r8 = lane & 7;
    int aoff = ((q8 & 1) * 8 + r8) * RS + (q8 >> 1) * 4;
    int boff = ((q8 & 2) * 4 + r8 + wid * 32) * RS + (q8 & 1) * 4;

    float acc[4][4][4];
#pragma unroll
    for (int mf = 0; mf < 4; mf++)
#pragma unroll
        for (int j = 0; j < 4; j++)
#pragma unroll
            for (int qq = 0; qq < 4; qq++) acc[mf][j][qq] = 0.f;

    // prologue: A(0) in regs; B(0) in flight
    float4 ar0 = *(const float4*)(Ag + (size_t)arow * NM + ac * 8);
    float4 ar1 = *(const float4*)(Ag + (size_t)arow * NM + ac * 8 + 4);
    issue_B(0, sbase + (OFF_B + 0 * B_ST) * 4, tid);

    for (int c = 0; c < NCHUNK; c++) {
        asm volatile("cp.async.wait_group 0;" ::: "memory");   // B(c) landed
        // store A(c) from regs (fp16, 8 cols -> uint4)
        {
            uint32_t* Ab = smem + OFF_A + (c & 1) * A_ST;
            uint4 u;
            u.x = pack_h2(ar0.x, ar0.y);
            u.y = pack_h2(ar0.z, ar0.w);
            u.z = pack_h2(ar1.x, ar1.y);
            u.w = pack_h2(ar1.z, ar1.w);
            *(uint4*)(Ab + arow * RS + ac * 4) = u;
        }
        __syncthreads();   // B(c)+A(c) visible; buf (c+1)&1 fully consumed
        if (c < NCHUNK - 1) {
            issue_B(c + 1, sbase + (OFF_B + ((c + 1) & 1) * B_ST) * 4, tid);
            int k0 = (c + 1) * KC;
            ar0 = *(const float4*)(Ag + (size_t)arow * NM + k0 + ac * 8);
            ar1 = *(const float4*)(Ag + (size_t)arow * NM + k0 + ac * 8 + 4);
        }

        uint32_t Abase = sbase + (OFF_A + (c & 1) * A_ST + aoff) * 4;
        uint32_t Bbase = sbase + (OFF_B + (c & 1) * B_ST + boff) * 4;
#pragma unroll
        for (int ks = 0; ks < 4; ks++) {
            int ko4 = ks * 8 * 4;   // byte offset for this k16 step
            unsigned af[4][4];
#pragma unroll
            for (int mf = 0; mf < 4; mf++)
                LDMX4(af[mf][0], af[mf][1], af[mf][2], af[mf][3],
                      Abase + ko4 + mf * 16 * RS * 4);
            unsigned bf[8];
            LDMX4(bf[0], bf[1], bf[2], bf[3], Bbase + ko4);
            LDMX4(bf[4], bf[5], bf[6], bf[7], Bbase + ko4 + 16 * RS * 4);
#pragma unroll
            for (int j = 0; j < 4; j++) {
                unsigned b0 = bf[j * 2], b1 = bf[j * 2 + 1];
#pragma unroll
                for (int mf = 0; mf < 4; mf++)
                    mma_f16(acc[mf][j][0], acc[mf][j][1], acc[mf][j][2], acc[mf][j][3],
                            af[mf][0], af[mf][1], af[mf][2], af[mf][3], b0, b1);
            }
        }
    }

    // epilogue 1: partial score rows for this warp's 32 cols
    float p0[4], p1[4];
#pragma unroll
    for (int mf = 0; mf < 4; mf++) { p0[mf] = 0.f; p1[mf] = 0.f; }
#pragma unroll
    for (int mf = 0; mf < 4; mf++)
#pragma unroll
        for (int j = 0; j < 4; j++) {
            int a0 = wid * 32 + j * 8 + 2 * tg;
            float w0 = wvs[a0], w1 = wvs[a0 + 1];
            float q0 = wqs[a0], q1 = wqs[a0 + 1];
            p0[mf] += w0 * tanhf(q0 + acc[mf][j][0]) + w1 * tanhf(q1 + acc[mf][j][1]);
            p1[mf] += w0 * tanhf(q0 + acc[mf][j][2]) + w1 * tanhf(q1 + acc[mf][j][3]);
        }
#pragma unroll
    for (int mf = 0; mf < 4; mf++) {
        p0[mf] += __shfl_xor_sync(0xffffffffu, p0[mf], 1);
        p0[mf] += __shfl_xor_sync(0xffffffffu, p0[mf], 2);
        p1[mf] += __shfl_xor_sync(0xffffffffu, p1[mf], 1);
        p1[mf] += __shfl_xor_sync(0xffffffffu, p1[mf], 2);
    }
    if (tg == 0) {
#pragma unroll
        for (int mf = 0; mf < 4; mf++) {
            spr[wid * 64 + mf * 16 + g]     = p0[mf];
            spr[wid * 64 + mf * 16 + 8 + g] = p1[mf];
        }
    }
    __syncthreads();
    if (tid < BM) {
        float s = 0.f;
#pragma unroll
        for (int w = 0; w < 16; w++) s += spr[w * 64 + tid];
        float e = expf(s);                       // no max-subtract: bounded
        alpha_un[b * NT + t0 + tid] = e;
        es[tid] = e;
    }
    __syncthreads();

    // epilogue 2: unnormalized context partial; t split across thread halves
    {
        float* pp = (float*)(smem + OFF_B);       // reuse B region (4KB)
        int half = tid >> 8;                       // 0: t<32, 1: t>=32
        int m = (tid & 255) * 4;
        const float* mp = mem + ((size_t)b * NT + t0 + half * 32) * NM + m;
        float4 cacc = {0.f, 0.f, 0.f, 0.f};
#pragma unroll 8
        for (int t = 0; t < 32; t++) {
            float e = es[half * 32 + t];
            float4 v = *(const float4*)(mp + (size_t)t * NM);
            cacc.x += e * v.x; cacc.y += e * v.y;
            cacc.z += e * v.z; cacc.w += e * v.w;
        }
        if (half) *(float4*)(pp + m) = cacc;
        __syncthreads();
        if (!half) {
            float4 o = *(const float4*)(pp + m);
            o.x += cacc.x; o.y += cacc.y; o.z += cacc.z; o.w += cacc.w;
            *(float4*)(g_ctxp + ((size_t)blockIdx.x * NB + b) * NM + m) = o;
        }
    }
}

// ---------------------------------------------------------------------------
// Kernel 3: finalize, 4x parallel per batch row (quarter q of alpha + ctx).
// Z computed redundantly per quarter with identical summation order ->
// bitwise-identical inv across quarters (deterministic).
// ---------------------------------------------------------------------------
__global__ __launch_bounds__(256) void finalize_kernel(
    float* __restrict__ alpha, float* __restrict__ ctx)
{
    __shared__ float red[8];
    int b = blockIdx.x >> 2, q = blockIdx.x & 3;
    int tid = threadIdx.x;
    float* arow = alpha + b * NT;

    float z = 0.f;
#pragma unroll
    for (int i = 0; i < NT / 256; i++) z += arow[tid + 256 * i];
#pragma unroll
    for (int o = 16; o; o >>= 1) z += __shfl_xor_sync(0xffffffffu, z, o);
    if ((tid & 31) == 0) red[tid >> 5] = z;
    __syncthreads();
    z = 0.f;
#pragma unroll
    for (int w = 0; w < 8; w++) z += red[w];
    float inv = 1.f / z;

    // normalize this quarter's 512 alpha entries
#pragma unroll
    for (int i = 0; i < 2; i++)
        arow[q * 512 + tid + 256 * i] *= inv;

    // this quarter's 256 ctx columns; reduce 32 slices
    int m = q * 256 + tid;
    float s = 0.f;
#pragma unroll 4
    for (int sl = 0; sl < NSLICE; sl++)
        s += g_ctxp[((size_t)sl * NB + b) * NM + m];
    ctx[b * NM + m] = s * inv;
}

// ---------------------------------------------------------------------------
extern "C" void kernel_launch(void* const* d_in, const int* in_sizes, int n_in,
                              void* d_out, int out_size) {
    const float* query  = (const float*)d_in[0];
    const float* memory = (const float*)d_in[1];
    const float* Wq     = (const float*)d_in[2];
    const float* Wm     = (const float*)d_in[3];
    const float* Wv     = (const float*)d_in[4];
    float* alpha = (float*)d_out;            // [64, 2048]
    float* ctx   = alpha + NB * NT;          // [64, 1024]

    cvt_wm_kernel<<<256, 256>>>(Wm);
    wq_kernel<<<dim3(4, NB), 128>>>(query, Wq);

    cudaFuncSetAttribute(score_kernel, cudaFuncAttributeMaxDynamicSharedMemorySize, SMEM_SZ);
    score_kernel<<<dim3(NSLICE, NB), 512, SMEM_SZ>>>(memory, Wv, alpha);

    finalize_kernel<<<NB * 4, 256>>>(alpha, ctx);
}

// round 15
// speedup vs baseline: 1.6804x; 1.0110x over previous
#include <cuda_runtime.h>
#include <cuda_fp16.h>
#include <cstdint>

#define NB 64
#define NT 2048
#define NM 1024
#define NA 512
#define NQ 1024

#define BM 64             // t-rows per CTA
#define KC 64             // k per stage (fp16: 4 MMA k-steps)
#define NCHUNK (NM / KC)  // 16
#define RS 36             // smem row stride in uints: conflict-free (shift 4/row), 16B-aligned
#define NBST 2            // B stages

#define A_ST (BM * RS)                   // 2304 uints per A stage
#define B_ST (NA * RS)                   // 18432 uints per B stage
#define OFF_A 0
#define OFF_B (2 * A_ST)                 // 4608
#define OFF_WQ (OFF_B + NBST * B_ST)     // floats from here
#define OFF_WV (OFF_WQ + NA)
#define OFF_SP (OFF_WV + NA)
#define OFF_ES (OFF_SP + 16 * 64)        // 64 exp(score) values
#define SMEM_WORDS (OFF_ES + 64)
#define SMEM_SZ (SMEM_WORDS * 4)         // ~171 KB

#define NSLICE (NT / BM)                 // 32 t-slices per batch

__device__ float g_wq[NB * NA];
__device__ uint32_t g_wm_h[NA * NM / 2];        // Wm as half2 pairs, [a][k/2]
__device__ float g_ctxp[NSLICE * NB * NM];      // context partials [slice][b][m]
__device__ float g_zp[NB * NSLICE];             // per-slice sum-of-exp partials

__device__ __forceinline__ uint32_t smem_u32(const void* p) {
    uint32_t a;
    asm("{ .reg .u64 t; cvta.to.shared.u64 t, %1; cvt.u32.u64 %0, t; }" : "=r"(a) : "l"(p));
    return a;
}

__device__ __forceinline__ void cpasync16(uint32_t dst, const void* src) {
    asm volatile("cp.async.cg.shared.global [%0], [%1], 16;" :: "r"(dst), "l"(src) : "memory");
}

__device__ __forceinline__ uint32_t pack_h2(float x, float y) {
    __half2 h = __floats2half2_rn(x, y);
    return *(uint32_t*)&h;
}

__device__ __forceinline__ void mma_f16(float& d0, float& d1, float& d2, float& d3,
                                        unsigned a0, unsigned a1, unsigned a2, unsigned a3,
                                        unsigned b0, unsigned b1) {
    asm("mma.sync.aligned.m16n8k16.row.col.f32.f16.f16.f32 "
        "{%0,%1,%2,%3},{%4,%5,%6,%7},{%8,%9},{%0,%1,%2,%3};"
        : "+f"(d0), "+f"(d1), "+f"(d2), "+f"(d3)
        : "r"(a0), "r"(a1), "r"(a2), "r"(a3), "r"(b0), "r"(b1));
}

#define LDMX4(r0, r1, r2, r3, addr) \
    asm volatile("ldmatrix.sync.aligned.m8n8.x4.shared.b16 {%0,%1,%2,%3}, [%4];" \
                 : "=r"(r0), "=r"(r1), "=r"(r2), "=r"(r3) : "r"(addr))

// ---------------------------------------------------------------------------
// Kernel 0: convert Wm (fp32) -> g_wm_h (half2 pairs)
// ---------------------------------------------------------------------------
__global__ void cvt_wm_kernel(const float* __restrict__ Wm) {
    int i = blockIdx.x * 256 + threadIdx.x;
    const float4* s = (const float4*)Wm;
    float4 v0 = s[2 * i], v1 = s[2 * i + 1];
    g_wm_h[4 * i + 0] = pack_h2(v0.x, v0.y);
    g_wm_h[4 * i + 1] = pack_h2(v0.z, v0.w);
    g_wm_h[4 * i + 2] = pack_h2(v1.x, v1.y);
    g_wm_h[4 * i + 3] = pack_h2(v1.z, v1.w);
}

// ---------------------------------------------------------------------------
// Kernel 1: wq[b][a] = query[b] . W_query[a]  (fp32 exact; 256 CTAs x 128 thr)
// ---------------------------------------------------------------------------
__global__ __launch_bounds__(128) void wq_kernel(
    const float* __restrict__ query, const float* __restrict__ Wq)
{
    int b = blockIdx.y, a = blockIdx.x * 128 + threadIdx.x;
    const float4* q4 = (const float4*)(query + b * NQ);
    const float4* w4 = (const float4*)(Wq + a * NQ);
    float s = 0.f;
#pragma unroll 8
    for (int k = 0; k < NQ / 4; k++) {
        float4 q = q4[k], w = w4[k];
        s += q.x * w.x + q.y * w.y + q.z * w.z + q.w * w.w;
    }
    g_wq[b * NA + a] = s;
}

// ---------------------------------------------------------------------------
// Kernel 2: fused fp16 mma.sync GEMM (64 x 512 x 1024) + Wv.tanh(wq+wm)
//           + exp + unnorm context partial + per-slice Z partial.
//           (R10 mainloop: measured best of 5 variants.)
// ---------------------------------------------------------------------------
__device__ __forceinline__ void issue_B(int c, uint32_t bbuf, int tid) {
    int k2 = c * (KC / 2);                    // uint offset within row
#pragma unroll
    for (int i = 0; i < 8; i++) {             // 512 rows x 8 x 16B = 64KB
        int e = tid + i * 512;
        int row = e >> 3, c16 = e & 7;
        cpasync16(bbuf + (row * RS + c16 * 4) * 4,
                  g_wm_h + (size_t)row * (NM / 2) + k2 + c16 * 4);
    }
    asm volatile("cp.async.commit_group;" ::: "memory");
}

__global__ __launch_bounds__(512, 1) void score_kernel(
    const float* __restrict__ mem, const float* __restrict__ Wv,
    float* __restrict__ alpha_un)
{
    extern __shared__ __align__(16) uint32_t smem[];
    uint32_t sbase = smem_u32(smem);
    float* wqs = (float*)(smem + OFF_WQ);
    float* wvs = (float*)(smem + OFF_WV);
    float* spr = (float*)(smem + OFF_SP);
    float* es  = (float*)(smem + OFF_ES);

    int tid = threadIdx.x, wid = tid >> 5, lane = tid & 31;
    int g = lane >> 2, tg = lane & 3;
    int b = blockIdx.y, t0 = blockIdx.x * BM;

    for (int i = tid; i < NA; i += 512) {
        wqs[i] = g_wq[b * NA + i];
        wvs[i] = Wv[i];
    }

    const float* Ag = mem + ((size_t)b * NT + t0) * NM;
    const int arow = tid >> 3, ac = tid & 7;   // A: 64 rows x 8 float4-pairs

    // ldmatrix lane-address components (uint offsets within a stage)
    int q8 = lane >> 3, r8 = lane & 7;
    int aoff = ((q8 & 1) * 8 + r8) * RS + (q8 >> 1) * 4;
    int boff = ((q8 & 2) * 4 + r8 + wid * 32) * RS + (q8 & 1) * 4;

    float acc[4][4][4];
#pragma unroll
    for (int mf = 0; mf < 4; mf++)
#pragma unroll
        for (int j = 0; j < 4; j++)
#pragma unroll
            for (int qq = 0; qq < 4; qq++) acc[mf][j][qq] = 0.f;

    // prologue: A(0) in regs; B(0) in flight
    float4 ar0 = *(const float4*)(Ag + (size_t)arow * NM + ac * 8);
    float4 ar1 = *(const float4*)(Ag + (size_t)arow * NM + ac * 8 + 4);
    issue_B(0, sbase + (OFF_B + 0 * B_ST) * 4, tid);

    for (int c = 0; c < NCHUNK; c++) {
        asm volatile("cp.async.wait_group 0;" ::: "memory");   // B(c) landed
        // store A(c) from regs (fp16, 8 cols -> uint4)
        {
            uint32_t* Ab = smem + OFF_A + (c & 1) * A_ST;
            uint4 u;
            u.x = pack_h2(ar0.x, ar0.y);
            u.y = pack_h2(ar0.z, ar0.w);
            u.z = pack_h2(ar1.x, ar1.y);
            u.w = pack_h2(ar1.z, ar1.w);
            *(uint4*)(Ab + arow * RS + ac * 4) = u;
        }
        __syncthreads();   // B(c)+A(c) visible; buf (c+1)&1 fully consumed
        if (c < NCHUNK - 1) {
            issue_B(c + 1, sbase + (OFF_B + ((c + 1) & 1) * B_ST) * 4, tid);
            int k0 = (c + 1) * KC;
            ar0 = *(const float4*)(Ag + (size_t)arow * NM + k0 + ac * 8);
            ar1 = *(const float4*)(Ag + (size_t)arow * NM + k0 + ac * 8 + 4);
        }

        uint32_t Abase = sbase + (OFF_A + (c & 1) * A_ST + aoff) * 4;
        uint32_t Bbase = sbase + (OFF_B + (c & 1) * B_ST + boff) * 4;
#pragma unroll
        for (int ks = 0; ks < 4; ks++) {
            int ko4 = ks * 8 * 4;   // byte offset for this k16 step
            unsigned af[4][4];
#pragma unroll
            for (int mf = 0; mf < 4; mf++)
                LDMX4(af[mf][0], af[mf][1], af[mf][2], af[mf][3],
                      Abase + ko4 + mf * 16 * RS * 4);
            unsigned bf[8];
            LDMX4(bf[0], bf[1], bf[2], bf[3], Bbase + ko4);
            LDMX4(bf[4], bf[5], bf[6], bf[7], Bbase + ko4 + 16 * RS * 4);
#pragma unroll
            for (int j = 0; j < 4; j++) {
                unsigned b0 = bf[j * 2], b1 = bf[j * 2 + 1];
#pragma unroll
                for (int mf = 0; mf < 4; mf++)
                    mma_f16(acc[mf][j][0], acc[mf][j][1], acc[mf][j][2], acc[mf][j][3],
                            af[mf][0], af[mf][1], af[mf][2], af[mf][3], b0, b1);
            }
        }
    }

    // epilogue 1: partial score rows for this warp's 32 cols
    float p0[4], p1[4];
#pragma unroll
    for (int mf = 0; mf < 4; mf++) { p0[mf] = 0.f; p1[mf] = 0.f; }
#pragma unroll
    for (int mf = 0; mf < 4; mf++)
#pragma unroll
        for (int j = 0; j < 4; j++) {
            int a0 = wid * 32 + j * 8 + 2 * tg;
            float w0 = wvs[a0], w1 = wvs[a0 + 1];
            float q0 = wqs[a0], q1 = wqs[a0 + 1];
            p0[mf] += w0 * tanhf(q0 + acc[mf][j][0]) + w1 * tanhf(q1 + acc[mf][j][1]);
            p1[mf] += w0 * tanhf(q0 + acc[mf][j][2]) + w1 * tanhf(q1 + acc[mf][j][3]);
        }
#pragma unroll
    for (int mf = 0; mf < 4; mf++) {
        p0[mf] += __shfl_xor_sync(0xffffffffu, p0[mf], 1);
        p0[mf] += __shfl_xor_sync(0xffffffffu, p0[mf], 2);
        p1[mf] += __shfl_xor_sync(0xffffffffu, p1[mf], 1);
        p1[mf] += __shfl_xor_sync(0xffffffffu, p1[mf], 2);
    }
    if (tg == 0) {
#pragma unroll
        for (int mf = 0; mf < 4; mf++) {
            spr[wid * 64 + mf * 16 + g]     = p0[mf];
            spr[wid * 64 + mf * 16 + 8 + g] = p1[mf];
        }
    }
    __syncthreads();
    if (tid < BM) {
        float s = 0.f;
#pragma unroll
        for (int w = 0; w < 16; w++) s += spr[w * 64 + tid];
        float e = expf(s);                       // no max-subtract: bounded
        alpha_un[b * NT + t0 + tid] = e;
        es[tid] = e;
    }
    __syncthreads();

    // per-slice Z partial: warp 0 reduces es[0..63] in fixed order
    if (wid == 0) {
        float z = es[lane] + es[lane + 32];
#pragma unroll
        for (int o = 16; o; o >>= 1) z += __shfl_xor_sync(0xffffffffu, z, o);
        if (lane == 0) g_zp[b * NSLICE + blockIdx.x] = z;
    }

    // epilogue 2: unnormalized context partial; t split across thread halves
    {
        float* pp = (float*)(smem + OFF_B);       // reuse B region (4KB)
        int half = tid >> 8;                       // 0: t<32, 1: t>=32
        int m = (tid & 255) * 4;
        const float* mp = mem + ((size_t)b * NT + t0 + half * 32) * NM + m;
        float4 cacc = {0.f, 0.f, 0.f, 0.f};
#pragma unroll 8
        for (int t = 0; t < 32; t++) {
            float e = es[half * 32 + t];
            float4 v = *(const float4*)(mp + (size_t)t * NM);
            cacc.x += e * v.x; cacc.y += e * v.y;
            cacc.z += e * v.z; cacc.w += e * v.w;
        }
        if (half) *(float4*)(pp + m) = cacc;
        __syncthreads();
        if (!half) {
            float4 o = *(const float4*)(pp + m);
            o.x += cacc.x; o.y += cacc.y; o.z += cacc.z; o.w += cacc.w;
            *(float4*)(g_ctxp + ((size_t)blockIdx.x * NB + b) * NM + m) = o;
        }
    }
}

// ---------------------------------------------------------------------------
// Kernel 3: finalize, 4x parallel per batch row (quarter q of alpha + ctx).
// Z from the 32 per-slice partials (128B, fixed order -> bitwise-identical
// inv across the 4 quarter-blocks; no alpha-row streaming).
// ---------------------------------------------------------------------------
__global__ __launch_bounds__(256) void finalize_kernel(
    float* __restrict__ alpha, float* __restrict__ ctx)
{
    int b = blockIdx.x >> 2, q = blockIdx.x & 3;
    int tid = threadIdx.x;

    float z = 0.f;
#pragma unroll
    for (int sl = 0; sl < NSLICE; sl++)          // fixed scalar order, all blocks identical
        z += g_zp[b * NSLICE + sl];
    float inv = 1.f / z;

    // normalize this quarter's 512 alpha entries
    float* arow = alpha + b * NT;
#pragma unroll
    for (int i = 0; i < 2; i++)
        arow[q * 512 + tid + 256 * i] *= inv;

    // this quarter's 256 ctx columns; reduce 32 slices
    int m = q * 256 + tid;
    float s = 0.f;
#pragma unroll 4
    for (int sl = 0; sl < NSLICE; sl++)
        s += g_ctxp[((size_t)sl * NB + b) * NM + m];
    ctx[b * NM + m] = s * inv;
}

// ---------------------------------------------------------------------------
extern "C" void kernel_launch(void* const* d_in, const int* in_sizes, int n_in,
                              void* d_out, int out_size) {
    const float* query  = (const float*)d_in[0];
    const float* memory = (const float*)d_in[1];
    const float* Wq     = (const float*)d_in[2];
    const float* Wm     = (const float*)d_in[3];
    const float* Wv     = (const float*)d_in[4];
    float* alpha = (float*)d_out;            // [64, 2048]
    float* ctx   = alpha + NB * NT;          // [64, 1024]

    cvt_wm_kernel<<<256, 256>>>(Wm);
    wq_kernel<<<dim3(4, NB), 128>>>(query, Wq);

    cudaFuncSetAttribute(score_kernel, cudaFuncAttributeMaxDynamicSharedMemorySize, SMEM_SZ);
    score_kernel<<<dim3(NSLICE, NB), 512, SMEM_SZ>>>(memory, Wv, alpha);

    finalize_kernel<<<NB * 4, 256>>>(alpha, ctx);
}